// round 16
// baseline (speedup 1.0000x reference)
#include <cuda_runtime.h>
#include <cstdint>

// Problem constants (fixed by setup_inputs)
#define B      2
#define NPTS   8192
#define D      256
#define NBINS  32
#define BIN    256
#define TOPK   16
#define NPROJ  16          // n_bins / 2
#define NCHUNK (B * NBINS) // 64 total chunks across batches
#define KP     16          // k-panel depth for GEMM
#define NT     20          // tiles per chunk (64x32, j >= 2i)

// GEMM-side zero fill now covers the WHOLE output: [0, ZTOT) float4 = 512 MiB
#define ZTOT   ((long)B * NPTS * 2048)  // 33,554,432 float4
#define ZPB    26215                    // ceil(ZTOT / 1280) per gemm block
#define ZPS    26                       // stores/thread/panel (26*16*64 >= ZPB)

// ---------------- scratch (device globals; no allocation allowed) ------------
__device__ int   g_bin_idx[B * NPTS];
__device__ int   g_order  [B * NPTS];
__device__ float g_dm     [NCHUNK * BIN * BIN]; // 16 MB sigmoid(similarity)
__device__ int   g_dst    [B * NPTS * TOPK];    // top-k destination indices
__device__ float g_val    [B * NPTS * TOPK];    // top-k values

// 64x32 tile list over the 4(row) x 8(col) tile grid, keeping j >= 2i.
// Every chunk cell is covered by a tile or by a mirror write; overlapping
// double-writes are bitwise identical (products commute, same k-order).
__constant__ int c_TI20[NT] = {0,0,0,0,0,0,0,0, 1,1,1,1,1,1, 2,2,2,2, 3,3};
__constant__ int c_TJ20[NT] = {0,1,2,3,4,5,6,7, 2,3,4,5,6,7, 4,5,6,7, 6,7};

// ---------------- K1: projection + argmax over [proj, -proj] ------------------
__global__ __launch_bounds__(256) void k_proj_argmax(
    const float* __restrict__ x, const float* __restrict__ cb) {
    __shared__ float cbs[NPROJ][D];
    int tid = threadIdx.x;
    for (int e = tid; e < D * 32; e += 256) {
        int d = e >> 5, j = e & 31;
        float v = cb[e];
        if (j < NPROJ) cbs[j][d] = v;
    }
    __syncthreads();

    int warp = tid >> 5, lane = tid & 31;
    for (int i = 0; i < 8; i++) {
        int p = blockIdx.x * 64 + warp * 8 + i;
        const float* xr = x + (size_t)p * D;
        float acc[NPROJ];
#pragma unroll
        for (int j = 0; j < NPROJ; j++) acc[j] = 0.f;
#pragma unroll
        for (int k = 0; k < 8; k++) {
            int d = lane + 32 * k;
            float xv = xr[d];
#pragma unroll
            for (int j = 0; j < NPROJ; j++) acc[j] += xv * cbs[j][d];
        }
#pragma unroll
        for (int j = 0; j < NPROJ; j++)
#pragma unroll
            for (int off = 16; off; off >>= 1)
                acc[j] += __shfl_xor_sync(0xFFFFFFFFu, acc[j], off);
        if (lane == 0) {
            float best = acc[0]; int bi = 0;
            for (int jj = 1; jj < 2 * NPROJ; jj++) {
                float v = (jj < NPROJ) ? acc[jj] : -acc[jj - NPROJ];
                if (v > best) { best = v; bi = jj; }
            }
            g_bin_idx[p] = bi;
        }
    }
}

// ---------------- K2: stable counting sort (smem-staged ballots) --------------
__global__ __launch_bounds__(1024) void k_stable_sort() {
    __shared__ int sbin[NPTS];      // 32 KB
    __shared__ int off[NBINS + 1];

    int batch = blockIdx.x;
    const int4* bi4 = (const int4*)(g_bin_idx + batch * NPTS);
    int4* sb4 = (int4*)sbin;
    for (int i = threadIdx.x; i < NPTS / 4; i += 1024) sb4[i] = bi4[i];
    __syncthreads();

    int* ord = g_order + batch * NPTS;
    int w = threadIdx.x >> 5, lane = threadIdx.x & 31;

    int total = 0;
#pragma unroll 8
    for (int it = 0; it < NPTS / 32; it++) {
        unsigned m = __ballot_sync(0xFFFFFFFFu, sbin[it * 32 + lane] == w);
        total += __popc(m);
    }
    if (lane == 0) off[w + 1] = total;
    __syncthreads();
    if (threadIdx.x == 0) {
        off[0] = 0;
        for (int j = 1; j <= NBINS; j++) off[j] += off[j - 1];
    }
    __syncthreads();

    int pos = off[w];
#pragma unroll 4
    for (int it = 0; it < NPTS / 32; it++) {
        int i = it * 32 + lane;
        int b = sbin[i];
        unsigned m = __ballot_sync(0xFFFFFFFFu, b == w);
        if (b == w) ord[pos + __popc(m & ((1u << lane) - 1u))] = i;
        pos += __popc(m);
    }
}

// ---------------- K3: GEMM+sigmoid + full output zero (sprinkled) ------------
// 1280 blocks x 64 threads; validated compute. Each block also zeroes ZPB
// float4 of the output via fire-and-forget streaming stores interleaved with
// the k-panels (LSU-issue only; FFMA stream keeps going).
__global__ __launch_bounds__(64) void k_gemm_sym(const float* __restrict__ x,
                                                 float4* __restrict__ out4) {
    __shared__ float As[KP][68];
    __shared__ float Bs[KP][36];

    int t     = blockIdx.x % NT;
    int chunk = blockIdx.x / NT;
    int b     = chunk >> 5;
    int cbase = (chunk & 31) * BIN;
    int row0 = c_TI20[t] * 64, col0 = c_TJ20[t] * 32;

    int tid = threadIdx.x;
    int q = tid & 3;       // which float4 of the 16-wide k panel
    int rbase = tid >> 2;  // 0..15

    // zero-fill slice for this block
    long zbeg = (long)blockIdx.x * ZPB;
    long zend = zbeg + ZPB; if (zend > ZTOT) zend = ZTOT;
    const float4 z4 = make_float4(0.f, 0.f, 0.f, 0.f);

    const float* aptr[4];
    const float* bptr[2];
#pragma unroll
    for (int l = 0; l < 4; l++) {
        int sA = g_order[b * NPTS + cbase + row0 + rbase + 16 * l];
        aptr[l] = x + ((size_t)b * NPTS + sA) * D + q * 4;
    }
#pragma unroll
    for (int l = 0; l < 2; l++) {
        int sB = g_order[b * NPTS + cbase + col0 + rbase + 16 * l];
        bptr[l] = x + ((size_t)b * NPTS + sB) * D + q * 4;
    }

    int tx = tid & 7, ty = tid >> 3; // 8 col-groups of 4, 8 row-groups of 8

    float acc[8][4];
#pragma unroll
    for (int i = 0; i < 8; i++)
#pragma unroll
        for (int j = 0; j < 4; j++) acc[i][j] = 0.f;

    float4 va[4], vb[2];
#pragma unroll
    for (int l = 0; l < 4; l++) va[l] = *(const float4*)(aptr[l]);
#pragma unroll
    for (int l = 0; l < 2; l++) vb[l] = *(const float4*)(bptr[l]);

    int panel = 0;
    for (int kt = 0; kt < D; kt += KP, panel++) {
        __syncthreads(); // previous compute done reading smem
#pragma unroll
        for (int l = 0; l < 4; l++) {
            int r = rbase + 16 * l;
            As[q * 4 + 0][r] = va[l].x;
            As[q * 4 + 1][r] = va[l].y;
            As[q * 4 + 2][r] = va[l].z;
            As[q * 4 + 3][r] = va[l].w;
        }
#pragma unroll
        for (int l = 0; l < 2; l++) {
            int r = rbase + 16 * l;
            Bs[q * 4 + 0][r] = vb[l].x;
            Bs[q * 4 + 1][r] = vb[l].y;
            Bs[q * 4 + 2][r] = vb[l].z;
            Bs[q * 4 + 3][r] = vb[l].w;
        }
        __syncthreads();
        // sprinkled zero stores: 26 per thread per panel, bounds-checked
        {
            long zi = zbeg + (long)panel * (ZPS * 64) + tid;
#pragma unroll
            for (int s = 0; s < ZPS; s++) {
                if (zi < zend) __stcs(&out4[zi], z4);
                zi += 64;
            }
        }
        if (kt + KP < D) { // prefetch next panel while computing
#pragma unroll
            for (int l = 0; l < 4; l++) va[l] = *(const float4*)(aptr[l] + kt + KP);
#pragma unroll
            for (int l = 0; l < 2; l++) vb[l] = *(const float4*)(bptr[l] + kt + KP);
        }
#pragma unroll
        for (int kk = 0; kk < KP; kk++) {
            float4 a0 = *(const float4*)&As[kk][ty * 8];      // broadcast/phase
            float4 a1 = *(const float4*)&As[kk][ty * 8 + 4];
            float4 b0 = *(const float4*)&Bs[kk][tx * 4];      // sequential/phase
            float a[8] = {a0.x, a0.y, a0.z, a0.w, a1.x, a1.y, a1.z, a1.w};
            float bb[4] = {b0.x, b0.y, b0.z, b0.w};
#pragma unroll
            for (int i = 0; i < 8; i++)
#pragma unroll
                for (int j = 0; j < 4; j++) acc[i][j] += a[i] * bb[j];
        }
    }

    // sigmoid in place
#pragma unroll
    for (int i = 0; i < 8; i++)
#pragma unroll
        for (int j = 0; j < 4; j++)
            acc[i][j] = 1.f / (1.f + expf(-acc[i][j]));

    float* C = g_dm + (size_t)chunk * BIN * BIN;
    // normal tile write: one float4 per accumulator row
#pragma unroll
    for (int i = 0; i < 8; i++) {
        int rr = row0 + ty * 8 + i;
        *(float4*)(C + (size_t)rr * BIN + col0 + tx * 4) =
            make_float4(acc[i][0], acc[i][1], acc[i][2], acc[i][3]);
    }
    // mirror write (transposed); overlaps with other tiles are bit-identical
#pragma unroll
    for (int j = 0; j < 4; j++) {
        int rr = col0 + tx * 4 + j;
        *(float4*)(C + (size_t)rr * BIN + row0 + ty * 8) =
            make_float4(acc[0][j], acc[1][j], acc[2][j], acc[3][j]);
        *(float4*)(C + (size_t)rr * BIN + row0 + ty * 8 + 4) =
            make_float4(acc[4][j], acc[5][j], acc[6][j], acc[7][j]);
    }
}

// ---------------- K4: top-16 per row -> g_val/g_dst (no output access) -------
// one warp per row; 2048 blocks x 256 threads
__global__ __launch_bounds__(256) void k_topk() {
    int warp = threadIdx.x >> 5, lane = threadIdx.x & 31;
    int row_g = blockIdx.x * 8 + warp;   // [0, B*NPTS)
    const float* r = g_dm + (size_t)row_g * BIN;

    unsigned u[8];
#pragma unroll
    for (int q = 0; q < 8; q++) u[q] = __float_as_uint(r[lane + 32 * q]);

    int b = row_g >> 13;
    int jrow = row_g & (NPTS - 1);
    int chunkoff = b * NPTS + (jrow & ~(BIN - 1));

    for (int it = 0; it < TOPK; it++) {
        unsigned best = 0u; int bc = BIN;
#pragma unroll
        for (int q = 0; q < 8; q++) {
            // ascending c within lane + strict '>' keeps min col on ties
            if (u[q] > best) { best = u[q]; bc = lane + 32 * q; }
        }
        unsigned m = __reduce_max_sync(0xFFFFFFFFu, best);
        int cand = (best == m) ? bc : (1 << 30);
        int cmin = __reduce_min_sync(0xFFFFFFFFu, cand);
        if ((cmin & 31) == lane) u[cmin >> 5] = 0u; // sigmoid > 0: 0 == consumed
        if (lane == it) { // spread writes across lanes
            g_val[row_g * TOPK + it] = __uint_as_float(m);
            g_dst[row_g * TOPK + it] = g_order[chunkoff + cmin];
        }
    }
}

// ---------------- K5: apply the 262144 top-k stores (after zeroing) ----------
__global__ __launch_bounds__(256) void k_scatter(float* __restrict__ out) {
    int i = blockIdx.x * 256 + threadIdx.x; // [0, B*NPTS*TOPK)
    int row_g = i >> 4;
    int b = row_g >> 13;
    int gsrc = g_order[row_g];
    out[((size_t)b * NPTS + gsrc) * NPTS + g_dst[i]] = g_val[i];
}

// ---------------- launch ------------------------------------------------------
extern "C" void kernel_launch(void* const* d_in, const int* in_sizes, int n_in,
                              void* d_out, int out_size) {
    const float* x  = (const float*)d_in[0]; // (2, 8192, 256) f32
    const float* cb = (const float*)d_in[1]; // (256, 32) f32
    float* out = (float*)d_out;              // (2, 8192, 8192) f32

    k_proj_argmax<<<(B * NPTS) / 64, 256>>>(x, cb);
    k_stable_sort<<<B, 1024>>>();
    k_gemm_sym<<<NCHUNK * NT, 64>>>(x, (float4*)out);
    k_topk<<<(B * NPTS) / 8, 256>>>();
    k_scatter<<<(B * NPTS * TOPK) / 256, 256>>>(out);
}

// round 17
// speedup vs baseline: 1.1341x; 1.1341x over previous
#include <cuda_runtime.h>
#include <cstdint>

// Problem constants (fixed by setup_inputs)
#define B      2
#define NPTS   8192
#define D      256
#define NBINS  32
#define BIN    256
#define TOPK   16
#define NPROJ  16          // n_bins / 2
#define NCHUNK (B * NBINS) // 64 total chunks across batches
#define KP     16          // k-panel depth for GEMM
#define NT     20          // tiles per chunk (64x32, j >= 2i)

// GEMM-side zero fill: flat float4 range [0, ZTOT) == output batch 0 (256 MiB)
#define ZTOT   ((long)NPTS * 2048)      // 16,777,216 float4
#define ZPB    13108                     // ceil(ZTOT / 1280) per gemm block
#define ZPS    13                        // stores per thread per k-panel

// ---------------- scratch (device globals; no allocation allowed) ------------
__device__ int   g_bin_idx[B * NPTS];
__device__ int   g_order  [B * NPTS];
__device__ float g_dm     [NCHUNK * BIN * BIN]; // 16 MB sigmoid(similarity)
__device__ int   g_dst    [B * NPTS * TOPK];    // top-k destination indices
__device__ float g_val    [B * NPTS * TOPK];    // top-k values

// 64x32 tile list over the 4(row) x 8(col) tile grid, keeping j >= 2i.
// Every chunk cell is covered by a tile or by a mirror write; overlapping
// double-writes are bitwise identical (products commute, same k-order).
__constant__ int c_TI20[NT] = {0,0,0,0,0,0,0,0, 1,1,1,1,1,1, 2,2,2,2, 3,3};
__constant__ int c_TJ20[NT] = {0,1,2,3,4,5,6,7, 2,3,4,5,6,7, 4,5,6,7, 6,7};

// ---------------- K1: projection + argmax over [proj, -proj] ------------------
__global__ __launch_bounds__(256) void k_proj_argmax(
    const float* __restrict__ x, const float* __restrict__ cb) {
    __shared__ float cbs[NPROJ][D];
    int tid = threadIdx.x;
    for (int e = tid; e < D * 32; e += 256) {
        int d = e >> 5, j = e & 31;
        float v = cb[e];
        if (j < NPROJ) cbs[j][d] = v;
    }
    __syncthreads();

    int warp = tid >> 5, lane = tid & 31;
    for (int i = 0; i < 8; i++) {
        int p = blockIdx.x * 64 + warp * 8 + i;
        const float* xr = x + (size_t)p * D;
        float acc[NPROJ];
#pragma unroll
        for (int j = 0; j < NPROJ; j++) acc[j] = 0.f;
#pragma unroll
        for (int k = 0; k < 8; k++) {
            int d = lane + 32 * k;
            float xv = xr[d];
#pragma unroll
            for (int j = 0; j < NPROJ; j++) acc[j] += xv * cbs[j][d];
        }
#pragma unroll
        for (int j = 0; j < NPROJ; j++)
#pragma unroll
            for (int off = 16; off; off >>= 1)
                acc[j] += __shfl_xor_sync(0xFFFFFFFFu, acc[j], off);
        if (lane == 0) {
            float best = acc[0]; int bi = 0;
            for (int jj = 1; jj < 2 * NPROJ; jj++) {
                float v = (jj < NPROJ) ? acc[jj] : -acc[jj - NPROJ];
                if (v > best) { best = v; bi = jj; }
            }
            g_bin_idx[p] = bi;
        }
    }
}

// ---------------- K2: stable counting sort (smem-staged ballots) --------------
__global__ __launch_bounds__(1024) void k_stable_sort() {
    __shared__ int sbin[NPTS];      // 32 KB
    __shared__ int off[NBINS + 1];

    int batch = blockIdx.x;
    const int4* bi4 = (const int4*)(g_bin_idx + batch * NPTS);
    int4* sb4 = (int4*)sbin;
    for (int i = threadIdx.x; i < NPTS / 4; i += 1024) sb4[i] = bi4[i];
    __syncthreads();

    int* ord = g_order + batch * NPTS;
    int w = threadIdx.x >> 5, lane = threadIdx.x & 31;

    int total = 0;
#pragma unroll 8
    for (int it = 0; it < NPTS / 32; it++) {
        unsigned m = __ballot_sync(0xFFFFFFFFu, sbin[it * 32 + lane] == w);
        total += __popc(m);
    }
    if (lane == 0) off[w + 1] = total;
    __syncthreads();
    if (threadIdx.x == 0) {
        off[0] = 0;
        for (int j = 1; j <= NBINS; j++) off[j] += off[j - 1];
    }
    __syncthreads();

    int pos = off[w];
#pragma unroll 4
    for (int it = 0; it < NPTS / 32; it++) {
        int i = it * 32 + lane;
        int b = sbin[i];
        unsigned m = __ballot_sync(0xFFFFFFFFu, b == w);
        if (b == w) ord[pos + __popc(m & ((1u << lane) - 1u))] = i;
        pos += __popc(m);
    }
}

// ---------------- K3: GEMM+sigmoid + batch-0 zero (sprinkled, R15) -----------
__global__ __launch_bounds__(64) void k_gemm_sym(const float* __restrict__ x,
                                                 float4* __restrict__ out4) {
    __shared__ float As[KP][68];
    __shared__ float Bs[KP][36];

    int t     = blockIdx.x % NT;
    int chunk = blockIdx.x / NT;
    int b     = chunk >> 5;
    int cbase = (chunk & 31) * BIN;
    int row0 = c_TI20[t] * 64, col0 = c_TJ20[t] * 32;

    int tid = threadIdx.x;
    int q = tid & 3;       // which float4 of the 16-wide k panel
    int rbase = tid >> 2;  // 0..15

    // zero-fill slice for this block
    long zbeg = (long)blockIdx.x * ZPB;
    long zend = zbeg + ZPB; if (zend > ZTOT) zend = ZTOT;
    const float4 z4 = make_float4(0.f, 0.f, 0.f, 0.f);

    const float* aptr[4];
    const float* bptr[2];
#pragma unroll
    for (int l = 0; l < 4; l++) {
        int sA = g_order[b * NPTS + cbase + row0 + rbase + 16 * l];
        aptr[l] = x + ((size_t)b * NPTS + sA) * D + q * 4;
    }
#pragma unroll
    for (int l = 0; l < 2; l++) {
        int sB = g_order[b * NPTS + cbase + col0 + rbase + 16 * l];
        bptr[l] = x + ((size_t)b * NPTS + sB) * D + q * 4;
    }

    int tx = tid & 7, ty = tid >> 3; // 8 col-groups of 4, 8 row-groups of 8

    float acc[8][4];
#pragma unroll
    for (int i = 0; i < 8; i++)
#pragma unroll
        for (int j = 0; j < 4; j++) acc[i][j] = 0.f;

    float4 va[4], vb[2];
#pragma unroll
    for (int l = 0; l < 4; l++) va[l] = *(const float4*)(aptr[l]);
#pragma unroll
    for (int l = 0; l < 2; l++) vb[l] = *(const float4*)(bptr[l]);

    int panel = 0;
    for (int kt = 0; kt < D; kt += KP, panel++) {
        __syncthreads(); // previous compute done reading smem
#pragma unroll
        for (int l = 0; l < 4; l++) {
            int r = rbase + 16 * l;
            As[q * 4 + 0][r] = va[l].x;
            As[q * 4 + 1][r] = va[l].y;
            As[q * 4 + 2][r] = va[l].z;
            As[q * 4 + 3][r] = va[l].w;
        }
#pragma unroll
        for (int l = 0; l < 2; l++) {
            int r = rbase + 16 * l;
            Bs[q * 4 + 0][r] = vb[l].x;
            Bs[q * 4 + 1][r] = vb[l].y;
            Bs[q * 4 + 2][r] = vb[l].z;
            Bs[q * 4 + 3][r] = vb[l].w;
        }
        __syncthreads();
        // sprinkled zero stores: 13 per thread per panel, bounds-checked
        {
            long zi = zbeg + (long)panel * (ZPS * 64) + tid;
#pragma unroll
            for (int s = 0; s < ZPS; s++) {
                if (zi < zend) __stcs(&out4[zi], z4);
                zi += 64;
            }
        }
        if (kt + KP < D) { // prefetch next panel while computing
#pragma unroll
            for (int l = 0; l < 4; l++) va[l] = *(const float4*)(aptr[l] + kt + KP);
#pragma unroll
            for (int l = 0; l < 2; l++) vb[l] = *(const float4*)(bptr[l] + kt + KP);
        }
#pragma unroll
        for (int kk = 0; kk < KP; kk++) {
            float4 a0 = *(const float4*)&As[kk][ty * 8];      // broadcast/phase
            float4 a1 = *(const float4*)&As[kk][ty * 8 + 4];
            float4 b0 = *(const float4*)&Bs[kk][tx * 4];      // sequential/phase
            float a[8] = {a0.x, a0.y, a0.z, a0.w, a1.x, a1.y, a1.z, a1.w};
            float bb[4] = {b0.x, b0.y, b0.z, b0.w};
#pragma unroll
            for (int i = 0; i < 8; i++)
#pragma unroll
                for (int j = 0; j < 4; j++) acc[i][j] += a[i] * bb[j];
        }
    }

    // sigmoid in place
#pragma unroll
    for (int i = 0; i < 8; i++)
#pragma unroll
        for (int j = 0; j < 4; j++)
            acc[i][j] = 1.f / (1.f + expf(-acc[i][j]));

    float* C = g_dm + (size_t)chunk * BIN * BIN;
    // normal tile write: one float4 per accumulator row
#pragma unroll
    for (int i = 0; i < 8; i++) {
        int rr = row0 + ty * 8 + i;
        *(float4*)(C + (size_t)rr * BIN + col0 + tx * 4) =
            make_float4(acc[i][0], acc[i][1], acc[i][2], acc[i][3]);
    }
    // mirror write (transposed); overlaps with other tiles are bit-identical
#pragma unroll
    for (int j = 0; j < 4; j++) {
        int rr = col0 + tx * 4 + j;
        *(float4*)(C + (size_t)rr * BIN + row0 + ty * 8) =
            make_float4(acc[0][j], acc[1][j], acc[2][j], acc[3][j]);
        *(float4*)(C + (size_t)rr * BIN + row0 + ty * 8 + 4) =
            make_float4(acc[4][j], acc[5][j], acc[6][j], acc[7][j]);
    }
}

// ---------------- K4: balanced zero (batch 1) + top-16 ------------------------
// Every block zeroes exactly 16 KiB of batch 1: block jrow (batch 0) zeroes
// half [1024,2048) of batch-1 row jrow's target; block 8192+jrow zeroes half
// [0,1024) of its own row. Warp 0 does top-k for this block's row meanwhile.
__global__ __launch_bounds__(256) void k_zero_topk(float* __restrict__ out) {
    int row_g = blockIdx.x;              // [0, B*NPTS)
    int lane = threadIdx.x & 31, w = threadIdx.x >> 5;
    int b = row_g >> 13;
    int jrow = row_g & (NPTS - 1);

    // batch-1 partner row target (both sibling blocks resolve the same row)
    int gsrc1 = g_order[NPTS + jrow];
    float4* z4p = (float4*)(out + ((size_t)NPTS + gsrc1) * NPTS);
    int halfoff = (b == 0) ? 1024 : 0;
    const float4 z = make_float4(0.f, 0.f, 0.f, 0.f);

    if (w == 0) {
        const float* r = g_dm + (size_t)row_g * BIN;
        unsigned u[8];
#pragma unroll
        for (int q = 0; q < 8; q++) u[q] = __float_as_uint(r[lane + 32 * q]);
        int chunkoff = b * NPTS + (jrow & ~(BIN - 1));
        for (int it = 0; it < TOPK; it++) {
            unsigned best = 0u; int bc = BIN;
#pragma unroll
            for (int q = 0; q < 8; q++) {
                // ascending c within lane + strict '>' keeps min col on ties
                if (u[q] > best) { best = u[q]; bc = lane + 32 * q; }
            }
            unsigned m = __reduce_max_sync(0xFFFFFFFFu, best);
            int cand = (best == m) ? bc : (1 << 30);
            int cmin = __reduce_min_sync(0xFFFFFFFFu, cand);
            if ((cmin & 31) == lane) u[cmin >> 5] = 0u; // sigmoid > 0
            if (lane == it) {
                g_val[row_g * TOPK + it] = __uint_as_float(m);
                g_dst[row_g * TOPK + it] = g_order[chunkoff + cmin];
            }
        }
    } else {
        // warps 1-7 (224 threads) zero 1024 float4 of the assigned half
        for (int i = threadIdx.x - 32; i < 1024; i += 224)
            __stcs(&z4p[halfoff + i], z);
    }
}

// ---------------- K5: apply the 262144 top-k stores (after zeroing) ----------
__global__ __launch_bounds__(256) void k_scatter(float* __restrict__ out) {
    int i = blockIdx.x * 256 + threadIdx.x; // [0, B*NPTS*TOPK)
    int row_g = i >> 4;
    int b = row_g >> 13;
    int gsrc = g_order[row_g];
    out[((size_t)b * NPTS + gsrc) * NPTS + g_dst[i]] = g_val[i];
}

// ---------------- launch ------------------------------------------------------
extern "C" void kernel_launch(void* const* d_in, const int* in_sizes, int n_in,
                              void* d_out, int out_size) {
    const float* x  = (const float*)d_in[0]; // (2, 8192, 256) f32
    const float* cb = (const float*)d_in[1]; // (256, 32) f32
    float* out = (float*)d_out;              // (2, 8192, 8192) f32

    k_proj_argmax<<<(B * NPTS) / 64, 256>>>(x, cb);
    k_stable_sort<<<B, 1024>>>();
    k_gemm_sym<<<NCHUNK * NT, 64>>>(x, (float4*)out);
    k_zero_topk<<<B * NPTS, 256>>>(out);
    k_scatter<<<(B * NPTS * TOPK) / 256, 256>>>(out);
}